// round 16
// baseline (speedup 1.0000x reference)
#include <cuda_runtime.h>
#include <cuda_fp16.h>
#include <cstdint>

#define EPS 1e-3f

static constexpr int MROWS = 8192;   // B*H*W
static constexpr int CCH   = 512;
static constexpr int CH2   = 256;

// ---------------- scratch (device globals; no allocs allowed) ----------------
__device__ __align__(16) __half g_uvh[MROWS * CH2];

// fp16 GEMM-0 raw outputs (read by ur_k)
__device__ __align__(16) __half g_Ah [MROWS * CH2];
__device__ __align__(16) __half g_Pvh[MROWS * CH2];
__device__ __align__(16) __half g_Phh[MROWS * CH2];

__device__ __align__(16) __half g_xs[MROWS * CCH];
__device__ __align__(16) __half g_pv[MROWS * CCH];
__device__ __align__(16) __half g_ph[MROWS * CCH];
__device__ __align__(16) __half g_ag[MROWS * CCH];
__device__ __align__(16) __half g_up[MROWS * CH2];

__device__ __align__(16) __half g_vuT[256 * 1024];
__device__ __align__(16) __half g_wvT[256 *  512];
__device__ __align__(16) __half g_weT[256 *  512];
__device__ __align__(16) __half g_fcT[512 *  768];

__device__ __align__(16) float g_s2[CH2], g_t2[CH2], g_s3[CH2], g_t3[CH2];
__device__ __align__(16) float g_s5[CCH], g_t5[CCH];
__device__ float g_wr[4], g_cr;

// ---------------- PTX helpers ----------------
__device__ __forceinline__ uint32_t s2u(const void* p) {
    uint32_t a;
    asm("{ .reg .u64 t; cvta.to.shared.u64 t, %1; cvt.u32.u64 %0, t; }" : "=r"(a) : "l"(p));
    return a;
}
__device__ __forceinline__ void cpasync16(uint32_t s, const void* g) {
    asm volatile("cp.async.cg.shared.global [%0], [%1], 16;" :: "r"(s), "l"(g));
}
#define CP_COMMIT() asm volatile("cp.async.commit_group;" ::: "memory")
#define CP_WAIT(n)  asm volatile("cp.async.wait_group %0;" :: "n"(n) : "memory")

__device__ __forceinline__ void ldsm4(uint32_t* r, uint32_t addr) {
    asm volatile("ldmatrix.sync.aligned.m8n8.x4.shared.b16 {%0,%1,%2,%3}, [%4];"
                 : "=r"(r[0]), "=r"(r[1]), "=r"(r[2]), "=r"(r[3]) : "r"(addr));
}
__device__ __forceinline__ void mma16816(float* d, const uint32_t* a, const uint32_t* b) {
    asm volatile(
        "mma.sync.aligned.m16n8k16.row.col.f32.f16.f16.f32 "
        "{%0,%1,%2,%3}, {%4,%5,%6,%7}, {%8,%9}, {%0,%1,%2,%3};"
        : "+f"(d[0]), "+f"(d[1]), "+f"(d[2]), "+f"(d[3])
        : "r"(a[0]), "r"(a[1]), "r"(a[2]), "r"(a[3]), "r"(b[0]), "r"(b[1]));
}

// pack/unpack fp16 — bit-cast intrinsics only, no address-of locals
__device__ __forceinline__ uint32_t pk2(float a, float b) {
    return (uint32_t)__half_as_ushort(__float2half_rn(a)) |
           ((uint32_t)__half_as_ushort(__float2half_rn(b)) << 16);
}
__device__ __forceinline__ uint2 pk4(float4 v) {
    uint2 r;
    r.x = pk2(v.x, v.y);
    r.y = pk2(v.z, v.w);
    return r;
}
__device__ __forceinline__ float4 up4(uint2 r) {
    float4 v;
    v.x = __half2float(__ushort_as_half((unsigned short)(r.x & 0xFFFF)));
    v.y = __half2float(__ushort_as_half((unsigned short)(r.x >> 16)));
    v.z = __half2float(__ushort_as_half((unsigned short)(r.y & 0xFFFF)));
    v.w = __half2float(__ushort_as_half((unsigned short)(r.y >> 16)));
    return v;
}

// ---------------- fused prologue: aggsplit + 4x weight transpose + fold ---------
// agg processes BOTH batch images per thread (rows p and p+4096) for 2x MLP.
// block ranges: [0,2048) agg ; [2048,2304) W0 ; [2304,2432) W1 ;
// [2432,2560) W2 ; [2560,2944) W3 ; [2944] fold
template<int W>
__device__ __forceinline__ void prepw_body(const float* __restrict__ src,
                                           float (*t)[33], int bi, int tid) {
    constexpr int K = (W == 0) ? 1024 : ((W == 3) ? 768 : 512);
    constexpr int N = (W == 3) ? 512 : 256;
    constexpr int KB = K / 32;
    __half* dst = (W == 0) ? g_vuT : (W == 1) ? g_wvT : (W == 2) ? g_weT : g_fcT;
    const int k0 = (bi % KB) * 32, n0 = (bi / KB) * 32;
    const int r = tid >> 5, c = tid & 31;   // 8 x 32
    #pragma unroll
    for (int i = 0; i < 4; i++)
        t[r + 8 * i][c] = src[(size_t)(k0 + r + 8 * i) * N + n0 + c];
    __syncthreads();
    #pragma unroll
    for (int i = 0; i < 4; i++)
        dst[(size_t)(n0 + r + 8 * i) * K + k0 + c] = __float2half_rn(t[c][r + 8 * i]);
}

__global__ __launch_bounds__(256) void prep_all(
    const float* __restrict__ X,
    const float* w_ea, const float* b_ea,
    const float* g1, const float* b1, const float* m1, const float* v1,
    const float* w_vu, const float* b_vu,
    const float* g2, const float* b2, const float* m2, const float* v2,
    const float* w_eu, const float* b_eu,
    const float* g3, const float* b3, const float* m3, const float* v3,
    const float* w_er, const float* b_er,
    const float* g4, const float* b4, const float* m4, const float* v4,
    const float* w_fc,
    const float* g5, const float* b5, const float* m5, const float* v5) {
    __shared__ float t[32][33];
    const int b = blockIdx.x, tid = threadIdx.x;

    if (b < 2048) {
        float s1 = g1[0] * rsqrtf(v1[0] + EPS);
        float w0 = w_ea[0] * s1, w1 = w_ea[1] * s1, w2 = w_ea[2] * s1, w3 = w_ea[3] * s1;
        float ca = (b_ea[0] - m1[0]) * s1 + b1[0];

        int idx = b * 256 + tid;                 // over 4096*128 quads (batch 0 rows)
        int p0 = idx >> 7;                       // 0..4095
        int c = (idx & 127) << 2;
        int h = (p0 >> 6) & 63, w = p0 & 63;
        int baseH = p0 & ~4032;
        int pu0 = baseH | (((h + 63) & 63) << 6);
        int pd0 = baseH | (((h + 1) & 63) << 6);
        int baseW = p0 & ~63;
        int pl0 = baseW | ((w + 63) & 63);
        int pr0 = baseW | ((w + 1) & 63);

        // load both batch images up front: 10 independent 16B loads in flight
        float4 xv[2], xu[2], xd[2], xl[2], xr[2];
        #pragma unroll
        for (int q = 0; q < 2; q++) {
            int off = q * 4096;
            xv[q] = *(const float4*)(X + (size_t)(p0  + off) * 512 + c);
            xu[q] = *(const float4*)(X + (size_t)(pu0 + off) * 512 + c);
            xd[q] = *(const float4*)(X + (size_t)(pd0 + off) * 512 + c);
            xl[q] = *(const float4*)(X + (size_t)(pl0 + off) * 512 + c);
            xr[q] = *(const float4*)(X + (size_t)(pr0 + off) * 512 + c);
        }
        #pragma unroll
        for (int q = 0; q < 2; q++) {
            float4 v = xv[q], u = xu[q], dn = xd[q], l = xl[q], r = xr[q];
            float4 ag, pv, ph;
            ag.x = fmaxf(fmaf(v.x, w0 * u.x + w1 * dn.x + w2 * l.x + w3 * r.x, ca), 0.f);
            ag.y = fmaxf(fmaf(v.y, w0 * u.y + w1 * dn.y + w2 * l.y + w3 * r.y, ca), 0.f);
            ag.z = fmaxf(fmaf(v.z, w0 * u.z + w1 * dn.z + w2 * l.z + w3 * r.z, ca), 0.f);
            ag.w = fmaxf(fmaf(v.w, w0 * u.w + w1 * dn.w + w2 * l.w + w3 * r.w, ca), 0.f);
            pv = make_float4(v.x * u.x, v.y * u.y, v.z * u.z, v.w * u.w);
            ph = make_float4(v.x * l.x, v.y * l.y, v.z * l.z, v.w * l.w);
            size_t o = (size_t)(p0 + q * 4096) * 512 + c;
            *(uint2*)(g_xs + o) = pk4(v);
            *(uint2*)(g_pv + o) = pk4(pv);
            *(uint2*)(g_ph + o) = pk4(ph);
            *(uint2*)(g_ag + o) = pk4(ag);
        }
    } else if (b < 2304) {
        prepw_body<0>(w_vu, t, b - 2048, tid);
    } else if (b < 2432) {
        prepw_body<1>(w_eu, t, b - 2304, tid);
    } else if (b < 2560) {
        prepw_body<2>(w_eu + 512 * 256, t, b - 2432, tid);
    } else if (b < 2944) {
        prepw_body<3>(w_fc, t, b - 2560, tid);
    } else {
        int d = tid;
        if (d < CH2) {
            float s2 = g2[d] * rsqrtf(v2[d] + EPS);
            g_s2[d] = s2;
            g_t2[d] = (b_vu[d] - m2[d]) * s2 + b2[d];
            float s3 = g3[d] * rsqrtf(v3[d] + EPS);
            g_s3[d] = s3;
            g_t3[d] = (b_eu[d] - m3[d]) * s3 + b3[d];
        }
        #pragma unroll
        for (int dd = d; dd < CCH; dd += 256) {
            float s5 = g5[dd] * rsqrtf(v5[dd] + EPS);
            g_s5[dd] = s5;
            g_t5[dd] = b5[dd] - m5[dd] * s5;
        }
        if (d == 0) {
            float s4 = g4[0] * rsqrtf(v4[0] + EPS);
            #pragma unroll
            for (int n = 0; n < 4; n++) g_wr[n] = w_er[n] * s4;
            g_cr = (b_er[0] - m4[0]) * s4 + b4[0];
        }
    }
}

// ---------------- edge reduce + vertex*edge product (fp16 in -> fp16 upd) --------
__global__ void ur_k() {
    int idx = blockIdx.x * 256 + threadIdx.x;   // over 8192*64 quads
    int p = idx >> 6;
    int d = (idx & 63) << 2;
    int h = (p >> 6) & 63, w = p & 63;
    int pdn = (p & ~4032) | (((h + 1) & 63) << 6);
    int prt = (p & ~63)   | ((w + 1) & 63);
    const float4 A  = up4(*(const uint2*)(g_Ah  + (size_t)p   * 256 + d));
    const float4 e0 = up4(*(const uint2*)(g_Pvh + (size_t)p   * 256 + d));
    const float4 e1 = up4(*(const uint2*)(g_Pvh + (size_t)pdn * 256 + d));
    const float4 e2 = up4(*(const uint2*)(g_Phh + (size_t)p   * 256 + d));
    const float4 e3 = up4(*(const uint2*)(g_Phh + (size_t)prt * 256 + d));
    const float4 s3 = *(const float4*)(g_s3 + d);
    const float4 t3 = *(const float4*)(g_t3 + d);
    const float4 uv = up4(*(const uint2*)(g_uvh + (size_t)p * 256 + d));
    float w0 = g_wr[0], w1 = g_wr[1], w2 = g_wr[2], w3 = g_wr[3], cr = g_cr;
    float4 o;
#define UR_COMP(f)                                                      \
    {                                                                   \
        float u0 = fmaxf(fmaf(A.f + e0.f, s3.f, t3.f), 0.f);            \
        float u1 = fmaxf(fmaf(A.f + e1.f, s3.f, t3.f), 0.f);            \
        float u2 = fmaxf(fmaf(A.f + e2.f, s3.f, t3.f), 0.f);            \
        float u3 = fmaxf(fmaf(A.f + e3.f, s3.f, t3.f), 0.f);            \
        float rr = fmaxf(w0*u0 + w1*u1 + w2*u2 + w3*u3 + cr, 0.f);      \
        o.f = uv.f * rr;                                                \
    }
    UR_COMP(x) UR_COMP(y) UR_COMP(z) UR_COMP(w)
#undef UR_COMP
    *(uint2*)(g_up + (size_t)p * 256 + d) = pk4(o);
}

// ---------------- HMMA GEMM (mma.sync fp16, 128x128x32, 512 thr, 4 stages) ------
// PHASE 0 (flat 512-block grid, HEAVY-FIRST ordering):
//   blocks [0,128)   : z=3  [xs|ag]@vuT -> g_uvh (K=1024, 2x work — dispatched first)
//   blocks [128,512) : z=0,1,2  xs/pv/ph @ wvT/weT -> g_Ah/g_Pvh/g_Phh (K=512)
// PHASE 1: [xs|up]@fcT -> d_out (relu s5,t5), grid (64,4)
static constexpr int STAGE   = 16384;            // 8KB A + 8KB B
static constexpr int NSTG    = 4;
static constexpr int OFF_A   = 0;
static constexpr int OFF_B   = 8192;
static constexpr int SMEM_SZ = NSTG * STAGE;     // 65536

template<int PHASE>
__global__ __launch_bounds__(512, 1) void mma_gemm(float* __restrict__ OutFc) {
    extern __shared__ char sm[];
    const uint32_t sb = s2u(sm);
    const int tid = threadIdx.x, wid = tid >> 5, lane = tid & 31;

    int m0, n0, z;
    if (PHASE == 0) {
        const int bid = blockIdx.x;
        if (bid < 128) {                      // heavy slice first (K=1024)
            z = 3;
            m0 = (bid >> 1) * 128;
            n0 = (bid & 1) * 128;
        } else {
            const int t = bid - 128;
            z = t >> 7;                       // 0,1,2
            m0 = ((t >> 1) & 63) * 128;
            n0 = (t & 1) * 128;
        }
    } else {
        z = 4;
        m0 = blockIdx.x * 128;
        n0 = blockIdx.y * 128;
    }

    int KT;
    const __half* B_;
    if (PHASE == 0) {
        if (z == 0)      { KT = 512;  B_ = g_wvT; }
        else if (z == 1) { KT = 512;  B_ = g_weT; }
        else if (z == 2) { KT = 512;  B_ = g_weT; }
        else             { KT = 1024; B_ = g_vuT; }
    } else { KT = 768; B_ = g_fcT; }
    const int NIT = KT / 32;

    // per-thread cp.async coords: row = tid>>2 (0..127), chunk cc = tid&3
    const int lrow = tid >> 2;
    const int cc = tid & 3;
    const uint32_t so0 = (uint32_t)(lrow * 64 + ((cc ^ ((lrow >> 1) & 3)) << 4));

    auto load_stage = [&](int it) {
        const int k0 = it * 32;
        const uint32_t s = sb + (uint32_t)(it % NSTG) * STAGE;
        const __half* a_;
        int astr, ak;
        if (PHASE == 0) {
            if (z == 0)      { a_ = g_xs; astr = 512; ak = k0; }
            else if (z == 1) { a_ = g_pv; astr = 512; ak = k0; }
            else if (z == 2) { a_ = g_ph; astr = 512; ak = k0; }
            else {
                if (k0 < 512) { a_ = g_xs; astr = 512; ak = k0; }
                else          { a_ = g_ag; astr = 512; ak = k0 - 512; }
            }
        } else {
            if (k0 < 512) { a_ = g_xs; astr = 512; ak = k0; }
            else          { a_ = g_up; astr = 256; ak = k0 - 512; }
        }
        cpasync16(s + OFF_A + so0, a_ + (size_t)(m0 + lrow) * astr + ak + cc * 8);
        cpasync16(s + OFF_B + so0, B_ + (size_t)(n0 + lrow) * KT + k0 + cc * 8);
        CP_COMMIT();
    };

    const int wm = wid >> 2, wn = wid & 3;        // 4x4 warp grid, 32x32 each
    float acc[2][4][4];
    #pragma unroll
    for (int i = 0; i < 2; i++)
        #pragma unroll
        for (int j = 0; j < 4; j++)
            #pragma unroll
            for (int q = 0; q < 4; q++) acc[i][j][q] = 0.f;

    // frag ldsm coords
    const int arow_l = lane & 15;
    const int abump  = lane >> 4;                       // 0/1 -> chunk +0/+1
    const int brow_l = (lane & 7) + ((lane >> 4) << 3); // rows 0-7 / 8-15
    const int bbump  = (lane >> 3) & 1;

    auto compute = [&](int it) {
        const uint32_t s = sb + (uint32_t)(it % NSTG) * STAGE;
        #pragma unroll
        for (int ks = 0; ks < 2; ks++) {
            const int cb = ks * 2;
            uint32_t ah[2][4], bh[2][4];
            #pragma unroll
            for (int mt = 0; mt < 2; mt++) {
                int rr = wm * 32 + mt * 16 + arow_l;
                int ch = cb + abump;
                uint32_t ad = s + OFF_A + rr * 64 + ((ch ^ ((rr >> 1) & 3)) << 4);
                ldsm4(ah[mt], ad);
            }
            #pragma unroll
            for (int np = 0; np < 2; np++) {
                int rr = wn * 32 + np * 16 + brow_l;
                int ch = cb + bbump;
                uint32_t bd = s + OFF_B + rr * 64 + ((ch ^ ((rr >> 1) & 3)) << 4);
                ldsm4(bh[np], bd);
            }
            #pragma unroll
            for (int mt = 0; mt < 2; mt++)
                #pragma unroll
                for (int nt = 0; nt < 4; nt++)
                    mma16816(acc[mt][nt], ah[mt], &bh[nt >> 1][(nt & 1) * 2]);
        }
    };

    load_stage(0);
    load_stage(1);
    load_stage(2);
    for (int it = 0; it < NIT; it++) {
        if (it < NIT - 1) { CP_WAIT(2); } else { CP_WAIT(0); }
        __syncthreads();
        // next load targets slot (it+3)%4 == (it-1)%4; compute(it-1) finished
        // reading that slot before the barrier above
        if (it + 3 < NIT) load_stage(it + 3);
        compute(it);
    }

    // ---- epilogue ----
    #pragma unroll
    for (int mt = 0; mt < 2; mt++) {
        const int row = m0 + wm * 32 + mt * 16 + (lane >> 2);
        #pragma unroll
        for (int nt = 0; nt < 4; nt++) {
            const int lc = wn * 32 + nt * 8 + (lane & 3) * 2;
            const int gc = n0 + lc;
            float* d = acc[mt][nt];
            if (PHASE == 0 && z < 3) {
                __half* Out = (z == 0) ? g_Ah : (z == 1) ? g_Pvh : g_Phh;
                *(uint32_t*)(Out + (size_t)row * 256 + gc)       = pk2(d[0], d[1]);
                *(uint32_t*)(Out + (size_t)(row + 8) * 256 + gc) = pk2(d[2], d[3]);
            } else if (PHASE == 0) {
                float s0 = g_s2[gc], s1 = g_s2[gc + 1];
                float t0 = g_t2[gc], t1 = g_t2[gc + 1];
                *(uint32_t*)(g_uvh + (size_t)row * 256 + gc) =
                    pk2(fmaxf(fmaf(d[0], s0, t0), 0.f), fmaxf(fmaf(d[1], s1, t1), 0.f));
                *(uint32_t*)(g_uvh + (size_t)(row + 8) * 256 + gc) =
                    pk2(fmaxf(fmaf(d[2], s0, t0), 0.f), fmaxf(fmaf(d[3], s1, t1), 0.f));
            } else {
                float s0 = g_s5[gc], s1 = g_s5[gc + 1];
                float t0 = g_t5[gc], t1 = g_t5[gc + 1];
                *(float2*)(OutFc + (size_t)row * 512 + gc) =
                    make_float2(fmaxf(fmaf(d[0], s0, t0), 0.f), fmaxf(fmaf(d[1], s1, t1), 0.f));
                *(float2*)(OutFc + (size_t)(row + 8) * 512 + gc) =
                    make_float2(fmaxf(fmaf(d[2], s0, t0), 0.f), fmaxf(fmaf(d[3], s1, t1), 0.f));
            }
        }
    }
}

// ---------------- launch ----------------
extern "C" void kernel_launch(void* const* d_in, const int* in_sizes, int n_in,
                              void* d_out, int out_size) {
    const float* x    = (const float*)d_in[0];
    const float* w_ea = (const float*)d_in[1];
    const float* b_ea = (const float*)d_in[2];
    const float* g1   = (const float*)d_in[3];
    const float* b1   = (const float*)d_in[4];
    const float* m1   = (const float*)d_in[5];
    const float* v1   = (const float*)d_in[6];
    const float* w_vu = (const float*)d_in[7];
    const float* b_vu = (const float*)d_in[8];
    const float* g2   = (const float*)d_in[9];
    const float* b2   = (const float*)d_in[10];
    const float* m2   = (const float*)d_in[11];
    const float* v2   = (const float*)d_in[12];
    const float* w_eu = (const float*)d_in[13];
    const float* b_eu = (const float*)d_in[14];
    const float* g3   = (const float*)d_in[15];
    const float* b3   = (const float*)d_in[16];
    const float* m3   = (const float*)d_in[17];
    const float* v3   = (const float*)d_in[18];
    const float* w_er = (const float*)d_in[19];
    const float* b_er = (const float*)d_in[20];
    const float* g4   = (const float*)d_in[21];
    const float* b4   = (const float*)d_in[22];
    const float* m4   = (const float*)d_in[23];
    const float* v4   = (const float*)d_in[24];
    const float* w_fc = (const float*)d_in[25];
    const float* g5   = (const float*)d_in[26];
    const float* b5   = (const float*)d_in[27];
    const float* m5   = (const float*)d_in[28];
    const float* v5   = (const float*)d_in[29];

    cudaFuncSetAttribute((const void*)mma_gemm<0>,
                         cudaFuncAttributeMaxDynamicSharedMemorySize, SMEM_SZ);
    cudaFuncSetAttribute((const void*)mma_gemm<1>,
                         cudaFuncAttributeMaxDynamicSharedMemorySize, SMEM_SZ);

    prep_all<<<2945, 256>>>(x,
                            w_ea, b_ea, g1, b1, m1, v1,
                            w_vu, b_vu, g2, b2, m2, v2,
                            w_eu, b_eu, g3, b3, m3, v3,
                            w_er, b_er, g4, b4, m4, v4,
                            w_fc, g5, b5, m5, v5);

    // PHASE 0: flat grid, heavy (K=1024) tiles dispatched first
    mma_gemm<0><<<512, 512, SMEM_SZ>>>(nullptr);                // g_Ah,g_Pvh,g_Phh,g_uvh
    ur_k<<<2048, 256>>>();                                      // -> g_up (fp16)
    mma_gemm<1><<<dim3(64, 4, 1), 512, SMEM_SZ>>>((float*)d_out);
}

// round 17
// speedup vs baseline: 1.0192x; 1.0192x over previous
#include <cuda_runtime.h>
#include <cuda_fp16.h>
#include <cstdint>

#define EPS 1e-3f

static constexpr int MROWS = 8192;   // B*H*W
static constexpr int CCH   = 512;
static constexpr int CH2   = 256;

// ---------------- scratch (device globals; no allocs allowed) ----------------
__device__ __align__(16) __half g_uvh[MROWS * CH2];

// fp16 GEMM-0 raw outputs (read by ur_k)
__device__ __align__(16) __half g_Ah [MROWS * CH2];
__device__ __align__(16) __half g_Pvh[MROWS * CH2];
__device__ __align__(16) __half g_Phh[MROWS * CH2];

__device__ __align__(16) __half g_xs[MROWS * CCH];
__device__ __align__(16) __half g_pv[MROWS * CCH];
__device__ __align__(16) __half g_ph[MROWS * CCH];
__device__ __align__(16) __half g_ag[MROWS * CCH];
__device__ __align__(16) __half g_up[MROWS * CH2];

__device__ __align__(16) __half g_vuT[256 * 1024];
__device__ __align__(16) __half g_wvT[256 *  512];
__device__ __align__(16) __half g_weT[256 *  512];
__device__ __align__(16) __half g_fcT[512 *  768];

__device__ __align__(16) float g_s2[CH2], g_t2[CH2], g_s3[CH2], g_t3[CH2];
__device__ __align__(16) float g_s5[CCH], g_t5[CCH];
__device__ float g_wr[4], g_cr;

// ---------------- PTX helpers ----------------
__device__ __forceinline__ uint32_t s2u(const void* p) {
    uint32_t a;
    asm("{ .reg .u64 t; cvta.to.shared.u64 t, %1; cvt.u32.u64 %0, t; }" : "=r"(a) : "l"(p));
    return a;
}
__device__ __forceinline__ void cpasync16(uint32_t s, const void* g) {
    asm volatile("cp.async.cg.shared.global [%0], [%1], 16;" :: "r"(s), "l"(g));
}
#define CP_COMMIT() asm volatile("cp.async.commit_group;" ::: "memory")
#define CP_WAIT(n)  asm volatile("cp.async.wait_group %0;" :: "n"(n) : "memory")

__device__ __forceinline__ void ldsm4(uint32_t* r, uint32_t addr) {
    asm volatile("ldmatrix.sync.aligned.m8n8.x4.shared.b16 {%0,%1,%2,%3}, [%4];"
                 : "=r"(r[0]), "=r"(r[1]), "=r"(r[2]), "=r"(r[3]) : "r"(addr));
}
__device__ __forceinline__ void mma16816(float* d, const uint32_t* a, const uint32_t* b) {
    asm volatile(
        "mma.sync.aligned.m16n8k16.row.col.f32.f16.f16.f32 "
        "{%0,%1,%2,%3}, {%4,%5,%6,%7}, {%8,%9}, {%0,%1,%2,%3};"
        : "+f"(d[0]), "+f"(d[1]), "+f"(d[2]), "+f"(d[3])
        : "r"(a[0]), "r"(a[1]), "r"(a[2]), "r"(a[3]), "r"(b[0]), "r"(b[1]));
}

// pack/unpack fp16 — bit-cast intrinsics only, no address-of locals
__device__ __forceinline__ uint32_t pk2(float a, float b) {
    return (uint32_t)__half_as_ushort(__float2half_rn(a)) |
           ((uint32_t)__half_as_ushort(__float2half_rn(b)) << 16);
}
__device__ __forceinline__ uint2 pk4(float4 v) {
    uint2 r;
    r.x = pk2(v.x, v.y);
    r.y = pk2(v.z, v.w);
    return r;
}
__device__ __forceinline__ float4 up4(uint2 r) {
    float4 v;
    v.x = __half2float(__ushort_as_half((unsigned short)(r.x & 0xFFFF)));
    v.y = __half2float(__ushort_as_half((unsigned short)(r.x >> 16)));
    v.z = __half2float(__ushort_as_half((unsigned short)(r.y & 0xFFFF)));
    v.w = __half2float(__ushort_as_half((unsigned short)(r.y >> 16)));
    return v;
}

// ---------------- fused prologue: aggsplit + 4x weight transpose + fold ---------
// (R15-measured agg configuration: 1 item (4 elems) per thread, 4096 agg blocks)
template<int W>
__device__ __forceinline__ void prepw_body(const float* __restrict__ src,
                                           float (*t)[33], int bi, int tid) {
    constexpr int K = (W == 0) ? 1024 : ((W == 3) ? 768 : 512);
    constexpr int N = (W == 3) ? 512 : 256;
    constexpr int KB = K / 32;
    __half* dst = (W == 0) ? g_vuT : (W == 1) ? g_wvT : (W == 2) ? g_weT : g_fcT;
    const int k0 = (bi % KB) * 32, n0 = (bi / KB) * 32;
    const int r = tid >> 5, c = tid & 31;   // 8 x 32
    #pragma unroll
    for (int i = 0; i < 4; i++)
        t[r + 8 * i][c] = src[(size_t)(k0 + r + 8 * i) * N + n0 + c];
    __syncthreads();
    #pragma unroll
    for (int i = 0; i < 4; i++)
        dst[(size_t)(n0 + r + 8 * i) * K + k0 + c] = __float2half_rn(t[c][r + 8 * i]);
}

__global__ __launch_bounds__(256) void prep_all(
    const float* __restrict__ X,
    const float* w_ea, const float* b_ea,
    const float* g1, const float* b1, const float* m1, const float* v1,
    const float* w_vu, const float* b_vu,
    const float* g2, const float* b2, const float* m2, const float* v2,
    const float* w_eu, const float* b_eu,
    const float* g3, const float* b3, const float* m3, const float* v3,
    const float* w_er, const float* b_er,
    const float* g4, const float* b4, const float* m4, const float* v4,
    const float* w_fc,
    const float* g5, const float* b5, const float* m5, const float* v5) {
    __shared__ float t[32][33];
    const int b = blockIdx.x, tid = threadIdx.x;

    if (b < 4096) {
        float s1 = g1[0] * rsqrtf(v1[0] + EPS);
        float w0 = w_ea[0] * s1, w1 = w_ea[1] * s1, w2 = w_ea[2] * s1, w3 = w_ea[3] * s1;
        float ca = (b_ea[0] - m1[0]) * s1 + b1[0];

        int idx = b * 256 + tid;
        int p = idx >> 7;
        int c = (idx & 127) << 2;
        int h = (p >> 6) & 63, w = p & 63;
        int baseH = p & ~4032;
        int pu = baseH | (((h + 63) & 63) << 6);
        int pd = baseH | (((h + 1) & 63) << 6);
        int baseW = p & ~63;
        int pl = baseW | ((w + 63) & 63);
        int pr = baseW | ((w + 1) & 63);
        float4 xv = *(const float4*)(X + (size_t)p  * 512 + c);
        float4 xu = *(const float4*)(X + (size_t)pu * 512 + c);
        float4 xd = *(const float4*)(X + (size_t)pd * 512 + c);
        float4 xl = *(const float4*)(X + (size_t)pl * 512 + c);
        float4 xr = *(const float4*)(X + (size_t)pr * 512 + c);
        float4 ag, pv, ph;
        ag.x = fmaxf(fmaf(xv.x, w0 * xu.x + w1 * xd.x + w2 * xl.x + w3 * xr.x, ca), 0.f);
        ag.y = fmaxf(fmaf(xv.y, w0 * xu.y + w1 * xd.y + w2 * xl.y + w3 * xr.y, ca), 0.f);
        ag.z = fmaxf(fmaf(xv.z, w0 * xu.z + w1 * xd.z + w2 * xl.z + w3 * xr.z, ca), 0.f);
        ag.w = fmaxf(fmaf(xv.w, w0 * xu.w + w1 * xd.w + w2 * xl.w + w3 * xr.w, ca), 0.f);
        pv = make_float4(xv.x * xu.x, xv.y * xu.y, xv.z * xu.z, xv.w * xu.w);
        ph = make_float4(xv.x * xl.x, xv.y * xl.y, xv.z * xl.z, xv.w * xl.w);

        size_t o = (size_t)p * 512 + c;
        *(uint2*)(g_xs + o) = pk4(xv);
        *(uint2*)(g_pv + o) = pk4(pv);
        *(uint2*)(g_ph + o) = pk4(ph);
        *(uint2*)(g_ag + o) = pk4(ag);
    } else if (b < 4352) {
        prepw_body<0>(w_vu, t, b - 4096, tid);
    } else if (b < 4480) {
        prepw_body<1>(w_eu, t, b - 4352, tid);
    } else if (b < 4608) {
        prepw_body<2>(w_eu + 512 * 256, t, b - 4480, tid);
    } else if (b < 4992) {
        prepw_body<3>(w_fc, t, b - 4608, tid);
    } else {
        int d = tid;
        if (d < CH2) {
            float s2 = g2[d] * rsqrtf(v2[d] + EPS);
            g_s2[d] = s2;
            g_t2[d] = (b_vu[d] - m2[d]) * s2 + b2[d];
            float s3 = g3[d] * rsqrtf(v3[d] + EPS);
            g_s3[d] = s3;
            g_t3[d] = (b_eu[d] - m3[d]) * s3 + b3[d];
        }
        #pragma unroll
        for (int dd = d; dd < CCH; dd += 256) {
            float s5 = g5[dd] * rsqrtf(v5[dd] + EPS);
            g_s5[dd] = s5;
            g_t5[dd] = b5[dd] - m5[dd] * s5;
        }
        if (d == 0) {
            float s4 = g4[0] * rsqrtf(v4[0] + EPS);
            #pragma unroll
            for (int n = 0; n < 4; n++) g_wr[n] = w_er[n] * s4;
            g_cr = (b_er[0] - m4[0]) * s4 + b4[0];
        }
    }
}

// ---------------- edge reduce + vertex*edge product (fp16 in -> fp16 upd) --------
__global__ void ur_k() {
    int idx = blockIdx.x * 256 + threadIdx.x;   // over 8192*64 quads
    int p = idx >> 6;
    int d = (idx & 63) << 2;
    int h = (p >> 6) & 63, w = p & 63;
    int pdn = (p & ~4032) | (((h + 1) & 63) << 6);
    int prt = (p & ~63)   | ((w + 1) & 63);
    const float4 A  = up4(*(const uint2*)(g_Ah  + (size_t)p   * 256 + d));
    const float4 e0 = up4(*(const uint2*)(g_Pvh + (size_t)p   * 256 + d));
    const float4 e1 = up4(*(const uint2*)(g_Pvh + (size_t)pdn * 256 + d));
    const float4 e2 = up4(*(const uint2*)(g_Phh + (size_t)p   * 256 + d));
    const float4 e3 = up4(*(const uint2*)(g_Phh + (size_t)prt * 256 + d));
    const float4 s3 = *(const float4*)(g_s3 + d);
    const float4 t3 = *(const float4*)(g_t3 + d);
    const float4 uv = up4(*(const uint2*)(g_uvh + (size_t)p * 256 + d));
    float w0 = g_wr[0], w1 = g_wr[1], w2 = g_wr[2], w3 = g_wr[3], cr = g_cr;
    float4 o;
#define UR_COMP(f)                                                      \
    {                                                                   \
        float u0 = fmaxf(fmaf(A.f + e0.f, s3.f, t3.f), 0.f);            \
        float u1 = fmaxf(fmaf(A.f + e1.f, s3.f, t3.f), 0.f);            \
        float u2 = fmaxf(fmaf(A.f + e2.f, s3.f, t3.f), 0.f);            \
        float u3 = fmaxf(fmaf(A.f + e3.f, s3.f, t3.f), 0.f);            \
        float rr = fmaxf(w0*u0 + w1*u1 + w2*u2 + w3*u3 + cr, 0.f);      \
        o.f = uv.f * rr;                                                \
    }
    UR_COMP(x) UR_COMP(y) UR_COMP(z) UR_COMP(w)
#undef UR_COMP
    *(uint2*)(g_up + (size_t)p * 256 + d) = pk4(o);
}

// ---------------- HMMA GEMM (mma.sync fp16, 128x128x32, 512 thr, 4 stages) ------
// PHASE 0 (flat 512-block grid, HEAVY-FIRST ordering):
//   blocks [0,128)   : z=3  [xs|ag]@vuT -> g_uvh (K=1024, 2x work — dispatched first)
//   blocks [128,512) : z=0,1,2  xs/pv/ph @ wvT/weT -> g_Ah/g_Pvh/g_Phh (K=512)
// PHASE 1: [xs|up]@fcT -> d_out (relu s5,t5), grid (64,4)
static constexpr int STAGE   = 16384;            // 8KB A + 8KB B
static constexpr int NSTG    = 4;
static constexpr int OFF_A   = 0;
static constexpr int OFF_B   = 8192;
static constexpr int SMEM_SZ = NSTG * STAGE;     // 65536

template<int PHASE>
__global__ __launch_bounds__(512, 1) void mma_gemm(float* __restrict__ OutFc) {
    extern __shared__ char sm[];
    const uint32_t sb = s2u(sm);
    const int tid = threadIdx.x, wid = tid >> 5, lane = tid & 31;

    int m0, n0, z;
    if (PHASE == 0) {
        const int bid = blockIdx.x;
        if (bid < 128) {                      // heavy slice first (K=1024)
            z = 3;
            m0 = (bid >> 1) * 128;
            n0 = (bid & 1) * 128;
        } else {
            const int t = bid - 128;
            z = t >> 7;                       // 0,1,2
            m0 = ((t >> 1) & 63) * 128;
            n0 = (t & 1) * 128;
        }
    } else {
        z = 4;
        m0 = blockIdx.x * 128;
        n0 = blockIdx.y * 128;
    }

    int KT;
    const __half* B_;
    if (PHASE == 0) {
        if (z == 0)      { KT = 512;  B_ = g_wvT; }
        else if (z == 1) { KT = 512;  B_ = g_weT; }
        else if (z == 2) { KT = 512;  B_ = g_weT; }
        else             { KT = 1024; B_ = g_vuT; }
    } else { KT = 768; B_ = g_fcT; }
    const int NIT = KT / 32;

    // per-thread cp.async coords: row = tid>>2 (0..127), chunk cc = tid&3
    const int lrow = tid >> 2;
    const int cc = tid & 3;
    const uint32_t so0 = (uint32_t)(lrow * 64 + ((cc ^ ((lrow >> 1) & 3)) << 4));

    auto load_stage = [&](int it) {
        const int k0 = it * 32;
        const uint32_t s = sb + (uint32_t)(it % NSTG) * STAGE;
        const __half* a_;
        int astr, ak;
        if (PHASE == 0) {
            if (z == 0)      { a_ = g_xs; astr = 512; ak = k0; }
            else if (z == 1) { a_ = g_pv; astr = 512; ak = k0; }
            else if (z == 2) { a_ = g_ph; astr = 512; ak = k0; }
            else {
                if (k0 < 512) { a_ = g_xs; astr = 512; ak = k0; }
                else          { a_ = g_ag; astr = 512; ak = k0 - 512; }
            }
        } else {
            if (k0 < 512) { a_ = g_xs; astr = 512; ak = k0; }
            else          { a_ = g_up; astr = 256; ak = k0 - 512; }
        }
        cpasync16(s + OFF_A + so0, a_ + (size_t)(m0 + lrow) * astr + ak + cc * 8);
        cpasync16(s + OFF_B + so0, B_ + (size_t)(n0 + lrow) * KT + k0 + cc * 8);
        CP_COMMIT();
    };

    const int wm = wid >> 2, wn = wid & 3;        // 4x4 warp grid, 32x32 each
    float acc[2][4][4];
    #pragma unroll
    for (int i = 0; i < 2; i++)
        #pragma unroll
        for (int j = 0; j < 4; j++)
            #pragma unroll
            for (int q = 0; q < 4; q++) acc[i][j][q] = 0.f;

    // frag ldsm coords
    const int arow_l = lane & 15;
    const int abump  = lane >> 4;                       // 0/1 -> chunk +0/+1
    const int brow_l = (lane & 7) + ((lane >> 4) << 3); // rows 0-7 / 8-15
    const int bbump  = (lane >> 3) & 1;

    auto compute = [&](int it) {
        const uint32_t s = sb + (uint32_t)(it % NSTG) * STAGE;
        #pragma unroll
        for (int ks = 0; ks < 2; ks++) {
            const int cb = ks * 2;
            uint32_t ah[2][4], bh[2][4];
            #pragma unroll
            for (int mt = 0; mt < 2; mt++) {
                int rr = wm * 32 + mt * 16 + arow_l;
                int ch = cb + abump;
                uint32_t ad = s + OFF_A + rr * 64 + ((ch ^ ((rr >> 1) & 3)) << 4);
                ldsm4(ah[mt], ad);
            }
            #pragma unroll
            for (int np = 0; np < 2; np++) {
                int rr = wn * 32 + np * 16 + brow_l;
                int ch = cb + bbump;
                uint32_t bd = s + OFF_B + rr * 64 + ((ch ^ ((rr >> 1) & 3)) << 4);
                ldsm4(bh[np], bd);
            }
            #pragma unroll
            for (int mt = 0; mt < 2; mt++)
                #pragma unroll
                for (int nt = 0; nt < 4; nt++)
                    mma16816(acc[mt][nt], ah[mt], &bh[nt >> 1][(nt & 1) * 2]);
        }
    };

    load_stage(0);
    load_stage(1);
    load_stage(2);
    for (int it = 0; it < NIT; it++) {
        if (it < NIT - 1) { CP_WAIT(2); } else { CP_WAIT(0); }
        __syncthreads();
        // next load targets slot (it+3)%4 == (it-1)%4; compute(it-1) finished
        // reading that slot before the barrier above
        if (it + 3 < NIT) load_stage(it + 3);
        compute(it);
    }

    // ---- epilogue ----
    #pragma unroll
    for (int mt = 0; mt < 2; mt++) {
        const int row = m0 + wm * 32 + mt * 16 + (lane >> 2);
        #pragma unroll
        for (int nt = 0; nt < 4; nt++) {
            const int lc = wn * 32 + nt * 8 + (lane & 3) * 2;
            const int gc = n0 + lc;
            float* d = acc[mt][nt];
            if (PHASE == 0 && z < 3) {
                __half* Out = (z == 0) ? g_Ah : (z == 1) ? g_Pvh : g_Phh;
                *(uint32_t*)(Out + (size_t)row * 256 + gc)       = pk2(d[0], d[1]);
                *(uint32_t*)(Out + (size_t)(row + 8) * 256 + gc) = pk2(d[2], d[3]);
            } else if (PHASE == 0) {
                float s0 = g_s2[gc], s1 = g_s2[gc + 1];
                float t0 = g_t2[gc], t1 = g_t2[gc + 1];
                *(uint32_t*)(g_uvh + (size_t)row * 256 + gc) =
                    pk2(fmaxf(fmaf(d[0], s0, t0), 0.f), fmaxf(fmaf(d[1], s1, t1), 0.f));
                *(uint32_t*)(g_uvh + (size_t)(row + 8) * 256 + gc) =
                    pk2(fmaxf(fmaf(d[2], s0, t0), 0.f), fmaxf(fmaf(d[3], s1, t1), 0.f));
            } else {
                float s0 = g_s5[gc], s1 = g_s5[gc + 1];
                float t0 = g_t5[gc], t1 = g_t5[gc + 1];
                *(float2*)(OutFc + (size_t)row * 512 + gc) =
                    make_float2(fmaxf(fmaf(d[0], s0, t0), 0.f), fmaxf(fmaf(d[1], s1, t1), 0.f));
                *(float2*)(OutFc + (size_t)(row + 8) * 512 + gc) =
                    make_float2(fmaxf(fmaf(d[2], s0, t0), 0.f), fmaxf(fmaf(d[3], s1, t1), 0.f));
            }
        }
    }
}

// ---------------- launch ----------------
extern "C" void kernel_launch(void* const* d_in, const int* in_sizes, int n_in,
                              void* d_out, int out_size) {
    const float* x    = (const float*)d_in[0];
    const float* w_ea = (const float*)d_in[1];
    const float* b_ea = (const float*)d_in[2];
    const float* g1   = (const float*)d_in[3];
    const float* b1   = (const float*)d_in[4];
    const float* m1   = (const float*)d_in[5];
    const float* v1   = (const float*)d_in[6];
    const float* w_vu = (const float*)d_in[7];
    const float* b_vu = (const float*)d_in[8];
    const float* g2   = (const float*)d_in[9];
    const float* b2   = (const float*)d_in[10];
    const float* m2   = (const float*)d_in[11];
    const float* v2   = (const float*)d_in[12];
    const float* w_eu = (const float*)d_in[13];
    const float* b_eu = (const float*)d_in[14];
    const float* g3   = (const float*)d_in[15];
    const float* b3   = (const float*)d_in[16];
    const float* m3   = (const float*)d_in[17];
    const float* v3   = (const float*)d_in[18];
    const float* w_er = (const float*)d_in[19];
    const float* b_er = (const float*)d_in[20];
    const float* g4   = (const float*)d_in[21];
    const float* b4   = (const float*)d_in[22];
    const float* m4   = (const float*)d_in[23];
    const float* v4   = (const float*)d_in[24];
    const float* w_fc = (const float*)d_in[25];
    const float* g5   = (const float*)d_in[26];
    const float* b5   = (const float*)d_in[27];
    const float* m5   = (const float*)d_in[28];
    const float* v5   = (const float*)d_in[29];

    cudaFuncSetAttribute((const void*)mma_gemm<0>,
                         cudaFuncAttributeMaxDynamicSharedMemorySize, SMEM_SZ);
    cudaFuncSetAttribute((const void*)mma_gemm<1>,
                         cudaFuncAttributeMaxDynamicSharedMemorySize, SMEM_SZ);

    prep_all<<<4993, 256>>>(x,
                            w_ea, b_ea, g1, b1, m1, v1,
                            w_vu, b_vu, g2, b2, m2, v2,
                            w_eu, b_eu, g3, b3, m3, v3,
                            w_er, b_er, g4, b4, m4, v4,
                            w_fc, g5, b5, m5, v5);

    // PHASE 0: flat grid, heavy (K=1024) tiles dispatched first
    mma_gemm<0><<<512, 512, SMEM_SZ>>>(nullptr);                // g_Ah,g_Pvh,g_Phh,g_uvh
    ur_k<<<2048, 256>>>();                                      // -> g_up (fp16)
    mma_gemm<1><<<dim3(64, 4, 1), 512, SMEM_SZ>>>((float*)d_out);
}